// round 1
// baseline (speedup 1.0000x reference)
#include <cuda_runtime.h>
#include <math.h>

#define Bn 256
#define Fn 200
#define E1n 64
#define E2n 128
#define Hn 4
#define ROWS (Bn*Fn)              // 51200
#define ALPHAc 0.2f
#define NEGc -9000000000000000.0f

// scratch: h[h][b*F+f][e], si/sj[h][b*F+f]
__device__ float g_h[(size_t)Hn*ROWS*E2n];   // ~104.9 MB
__device__ float g_si[Hn*ROWS];
__device__ float g_sj[Hn*ROWS];

// ---------------------------------------------------------------------------
// Kernel 1: h[h, row, e] = sum_k x[row, k] * W[h, k, e]
// CTA: 64 rows x 128 cols, 256 threads (16x16), thread tile 4x8, loop heads.
// ---------------------------------------------------------------------------
__global__ __launch_bounds__(256) void k_proj(const float* __restrict__ x,
                                              const float* __restrict__ W) {
    extern __shared__ float sm[];
    float (*xs)[65] = (float(*)[65])sm;            // 64 x 65 (padded)
    float* ws = sm + 64*65;                        // 64 x 128

    int tid  = threadIdx.x;
    int row0 = blockIdx.x * 64;

    // load x tile (64x64) via float4, store padded
    const float4* xg = (const float4*)(x + (size_t)row0 * E1n);
    #pragma unroll
    for (int i = 0; i < 4; ++i) {
        int idx = tid + i * 256;                   // 0..1023
        float4 v = xg[idx];
        int r = idx >> 4, c = (idx & 15) << 2;
        xs[r][c] = v.x; xs[r][c+1] = v.y; xs[r][c+2] = v.z; xs[r][c+3] = v.w;
    }

    int tr = tid >> 4;          // 0..15 -> rows tr*4..tr*4+3
    int tc = tid & 15;          // 0..15 -> cols tc*8..tc*8+7

    for (int h = 0; h < Hn; ++h) {
        __syncthreads();        // xs ready / previous head's compute done
        const float4* wg = (const float4*)(W + (size_t)h * E1n * E2n);
        float4* ws4 = (float4*)ws;
        #pragma unroll
        for (int i = 0; i < 8; ++i) ws4[tid + i*256] = wg[tid + i*256];
        __syncthreads();

        float acc[4][8];
        #pragma unroll
        for (int i = 0; i < 4; ++i)
            #pragma unroll
            for (int j = 0; j < 8; ++j) acc[i][j] = 0.f;

        #pragma unroll 8
        for (int k = 0; k < E1n; ++k) {
            float xr[4];
            #pragma unroll
            for (int i = 0; i < 4; ++i) xr[i] = xs[tr*4 + i][k];
            float4 w0 = *(const float4*)&ws[k*E2n + tc*8];
            float4 w1 = *(const float4*)&ws[k*E2n + tc*8 + 4];
            #pragma unroll
            for (int i = 0; i < 4; ++i) {
                acc[i][0] += xr[i]*w0.x; acc[i][1] += xr[i]*w0.y;
                acc[i][2] += xr[i]*w0.z; acc[i][3] += xr[i]*w0.w;
                acc[i][4] += xr[i]*w1.x; acc[i][5] += xr[i]*w1.y;
                acc[i][6] += xr[i]*w1.z; acc[i][7] += xr[i]*w1.w;
            }
        }

        float* dst = g_h + ((size_t)h*ROWS + row0) * E2n;
        #pragma unroll
        for (int i = 0; i < 4; ++i) {
            size_t off = (size_t)(tr*4 + i)*E2n + tc*8;
            *(float4*)&dst[off]     = make_float4(acc[i][0], acc[i][1], acc[i][2], acc[i][3]);
            *(float4*)&dst[off + 4] = make_float4(acc[i][4], acc[i][5], acc[i][6], acc[i][7]);
        }
    }
}

// ---------------------------------------------------------------------------
// Kernel 2: si/sj row dots.  One warp per (h, row).
// ---------------------------------------------------------------------------
__global__ __launch_bounds__(256) void k_sisj(const float* __restrict__ a) {
    int warp = threadIdx.x >> 5, lane = threadIdx.x & 31;
    size_t r = (size_t)blockIdx.x * 8 + warp;      // 0 .. Hn*ROWS-1
    int h = (int)(r / ROWS);
    const float4* hr = (const float4*)(g_h + r * E2n);
    const float4* ar = (const float4*)(a + (size_t)h * 2 * E2n);
    float4 hv = hr[lane];
    float4 ai = ar[lane];
    float4 aj = ar[lane + 32];
    float pi = hv.x*ai.x + hv.y*ai.y + hv.z*ai.z + hv.w*ai.w;
    float pj = hv.x*aj.x + hv.y*aj.y + hv.z*aj.z + hv.w*aj.w;
    #pragma unroll
    for (int o = 16; o > 0; o >>= 1) {
        pi += __shfl_xor_sync(0xffffffffu, pi, o);
        pj += __shfl_xor_sync(0xffffffffu, pj, o);
    }
    if (lane == 0) { g_si[r] = pi; g_sj[r] = pj; }
}

// ---------------------------------------------------------------------------
// Kernel 3: fused masked-softmax attention + attn @ h.  CTA per (h, b).
// smem: h tile 200x128 f32, sj/si, attn tile 32x200, row scales.
// ---------------------------------------------------------------------------
__global__ __launch_bounds__(256) void k_attn(const float* __restrict__ adj,
                                              float* __restrict__ out) {
    extern __shared__ float smem[];
    float* hs     = smem;                 // 200*128
    float* sjs    = hs  + Fn*E2n;         // 200
    float* sis    = sjs + Fn;             // 200
    float* attn   = sis + Fn;             // 32*200 (unnormalized p)
    float* rscale = attn + 32*Fn;         // 32

    int h = blockIdx.x, b = blockIdx.y;
    int tid = threadIdx.x;
    size_t base = (size_t)h*ROWS + (size_t)b*Fn;

    // stage h[h,b,:,:] and si/sj
    const float4* hg = (const float4*)(g_h + base * E2n);
    float4* hs4 = (float4*)hs;
    for (int i = tid; i < Fn*E2n/4; i += 256) hs4[i] = hg[i];
    for (int i = tid; i < Fn; i += 256) { sjs[i] = g_sj[base + i]; sis[i] = g_si[base + i]; }
    __syncthreads();

    int warp = tid >> 5, lane = tid & 31;
    int grow2 = tid >> 4;                 // row-pair 0..15
    int gcol  = (tid & 15) * 8;           // 0..120

    for (int t0 = 0; t0 < Fn; t0 += 32) {
        // ---- score phase: each warp computes 4 rows ----
        #pragma unroll
        for (int rr = 0; rr < 4; ++rr) {
            int rt = warp*4 + rr;
            int f  = t0 + rt;
            if (f < Fn) {
                float sif = sis[f];
                const float* adjrow = adj + (size_t)f * Fn;
                float s[7];
                #pragma unroll
                for (int j = 0; j < 7; ++j) {
                    int y = j*32 + lane;
                    if (y < Fn) {
                        float z = sif + sjs[y];
                        float e = (z > 0.f) ? z : ALPHAc * z;
                        float m = adjrow[y];
                        float mk = (m > 0.f) ? m : NEGc;
                        s[j] = e * mk;
                    } else {
                        s[j] = -INFINITY;
                    }
                }
                float mx = s[0];
                #pragma unroll
                for (int j = 1; j < 7; ++j) mx = fmaxf(mx, s[j]);
                #pragma unroll
                for (int o = 16; o > 0; o >>= 1) mx = fmaxf(mx, __shfl_xor_sync(0xffffffffu, mx, o));
                float p[7], sum = 0.f;
                #pragma unroll
                for (int j = 0; j < 7; ++j) { p[j] = expf(s[j] - mx); sum += p[j]; }
                #pragma unroll
                for (int o = 16; o > 0; o >>= 1) sum += __shfl_xor_sync(0xffffffffu, sum, o);
                #pragma unroll
                for (int j = 0; j < 7; ++j) {
                    int y = j*32 + lane;
                    if (y < Fn) attn[rt*Fn + y] = p[j];
                }
                if (lane == 0) rscale[rt] = 1.f / sum;
            }
        }
        __syncthreads();

        // ---- GEMM phase: out[t0..t0+31, :] = attn(32x200) @ hs(200x128) ----
        int r0 = grow2 * 2;
        float acc0[8], acc1[8];
        #pragma unroll
        for (int j = 0; j < 8; ++j) { acc0[j] = 0.f; acc1[j] = 0.f; }
        const float* a0p = attn + (size_t)r0 * Fn;
        const float* a1p = attn + (size_t)(r0 + 1) * Fn;
        #pragma unroll 4
        for (int y = 0; y < Fn; ++y) {
            float4 h0 = *(const float4*)&hs[(size_t)y*E2n + gcol];
            float4 h1 = *(const float4*)&hs[(size_t)y*E2n + gcol + 4];
            float a0 = a0p[y];
            float a1 = a1p[y];
            acc0[0] += a0*h0.x; acc0[1] += a0*h0.y; acc0[2] += a0*h0.z; acc0[3] += a0*h0.w;
            acc0[4] += a0*h1.x; acc0[5] += a0*h1.y; acc0[6] += a0*h1.z; acc0[7] += a0*h1.w;
            acc1[0] += a1*h0.x; acc1[1] += a1*h0.y; acc1[2] += a1*h0.z; acc1[3] += a1*h0.w;
            acc1[4] += a1*h1.x; acc1[5] += a1*h1.y; acc1[6] += a1*h1.z; acc1[7] += a1*h1.w;
        }
        #pragma unroll
        for (int rr = 0; rr < 2; ++rr) {
            int f = t0 + r0 + rr;
            if (f < Fn) {
                float sc = rscale[r0 + rr];
                float* ap = rr ? acc1 : acc0;
                size_t o = ((size_t)b*Fn + f) * (Hn*E2n) + (size_t)h*E2n + gcol;
                *(float4*)&out[o]     = make_float4(ap[0]*sc, ap[1]*sc, ap[2]*sc, ap[3]*sc);
                *(float4*)&out[o + 4] = make_float4(ap[4]*sc, ap[5]*sc, ap[6]*sc, ap[7]*sc);
            }
        }
        __syncthreads();   // protect attn/rscale before next tile overwrites
    }
}

// ---------------------------------------------------------------------------

extern "C" void kernel_launch(void* const* d_in, const int* in_sizes, int n_in,
                              void* d_out, int out_size) {
    const float* x   = (const float*)d_in[0];
    const float* adj = (const float*)d_in[1];
    const float* W   = (const float*)d_in[2];
    const float* a   = (const float*)d_in[3];
    float* out = (float*)d_out;

    const int SMEM_A = (64*65 + 64*128) * 4;                       // 49,408 B
    const int SMEM_B = (Fn*E2n + Fn + Fn + 32*Fn + 32) * 4;        // 129,728 B
    cudaFuncSetAttribute(k_proj, cudaFuncAttributeMaxDynamicSharedMemorySize, SMEM_A);
    cudaFuncSetAttribute(k_attn, cudaFuncAttributeMaxDynamicSharedMemorySize, SMEM_B);

    k_proj<<<ROWS/64, 256, SMEM_A>>>(x, W);                 // 800 CTAs
    k_sisj<<<(Hn*ROWS)/8, 256>>>(a);                        // 25,600 CTAs
    k_attn<<<dim3(Hn, Bn), 256, SMEM_B>>>(adj, out);        // 1,024 CTAs
}

// round 2
// speedup vs baseline: 1.9908x; 1.9908x over previous
#include <cuda_runtime.h>
#include <math.h>

#define Bn 256
#define Fn 200
#define E1n 64
#define E2n 128
#define Hn 4
#define ROWS (Bn*Fn)              // 51200
#define ALPHAc 0.2f
#define NEGc -9000000000000000.0f
#define AP 132                    // attnT row pad (multiple of 4, 4-way STS conflict ok)

typedef unsigned long long ull;

__device__ float g_h[(size_t)Hn*ROWS*E2n];   // ~104.9 MB
__device__ float g_si[Hn*ROWS];
__device__ float g_sj[Hn*ROWS];

// ---- packed f32x2 helpers ----
__device__ __forceinline__ ull dup2(float v) {
    ull r; asm("mov.b64 %0, {%1, %1};" : "=l"(r) : "f"(v)); return r;
}
__device__ __forceinline__ void fma2(ull &d, ull a, ull b) {
    asm("fma.rn.f32x2 %0, %1, %2, %0;" : "+l"(d) : "l"(a), "l"(b));
}
__device__ __forceinline__ float2 unpk(ull v) {
    float2 r; asm("mov.b64 {%0, %1}, %2;" : "=f"(r.x), "=f"(r.y) : "l"(v)); return r;
}
__device__ __forceinline__ ull d2l(double d) { return __double_as_longlong(d); }

// ---------------------------------------------------------------------------
// Kernel 1: h[h,row,e] = sum_k x[row,k] * W[h,k,e], plus si/sj epilogue.
// CTA: 128 rows x 128 cols, 256 threads, thread tile 8x8 (f32x2 packed).
// ---------------------------------------------------------------------------
__global__ __launch_bounds__(256) void k_proj(const float* __restrict__ x,
                                              const float* __restrict__ W,
                                              const float* __restrict__ a) {
    extern __shared__ float sm[];
    float* xs = sm;               // [128][65]
    float* ws = sm + 128*65;      // [64][128]

    int tid  = threadIdx.x;
    int row0 = blockIdx.x * 128;

    // load x tile 128x64
    const float4* xg = (const float4*)(x + (size_t)row0 * E1n);
    #pragma unroll
    for (int i = 0; i < 8; ++i) {
        int idx = tid + i * 256;                  // 0..2047
        float4 v = xg[idx];
        int r = idx >> 4, c = (idx & 15) << 2;
        float* p = &xs[r*65 + c];
        p[0] = v.x; p[1] = v.y; p[2] = v.z; p[3] = v.w;
    }

    int tr = tid >> 4;            // row group: rows tr*8 .. tr*8+7
    int tc = tid & 15;            // col group: cols tc*8 .. tc*8+7

    for (int h = 0; h < Hn; ++h) {
        __syncthreads();
        const float4* wg = (const float4*)(W + (size_t)h * E1n * E2n);
        float4* ws4 = (float4*)ws;
        #pragma unroll
        for (int i = 0; i < 8; ++i) ws4[tid + i*256] = wg[tid + i*256];
        __syncthreads();

        ull acc[32];
        #pragma unroll
        for (int i = 0; i < 32; ++i) acc[i] = 0ull;

        #pragma unroll 2
        for (int k = 0; k < E1n; ++k) {
            ull xd[8];
            #pragma unroll
            for (int r = 0; r < 8; ++r) xd[r] = dup2(xs[(tr*8 + r)*65 + k]);
            double2 w0 = *(const double2*)&ws[k*E2n + tc*8];
            double2 w1 = *(const double2*)&ws[k*E2n + tc*8 + 4];
            ull wv0 = d2l(w0.x), wv1 = d2l(w0.y), wv2 = d2l(w1.x), wv3 = d2l(w1.y);
            #pragma unroll
            for (int r = 0; r < 8; ++r) {
                fma2(acc[r*4+0], xd[r], wv0);
                fma2(acc[r*4+1], xd[r], wv1);
                fma2(acc[r*4+2], xd[r], wv2);
                fma2(acc[r*4+3], xd[r], wv3);
            }
        }

        // epilogue: store h, compute si/sj partial dots + 16-lane reduce
        const float* ap = a + (size_t)h * 2 * E2n;
        float4 ai0 = *(const float4*)&ap[tc*8];
        float4 ai1 = *(const float4*)&ap[tc*8 + 4];
        float4 aj0 = *(const float4*)&ap[E2n + tc*8];
        float4 aj1 = *(const float4*)&ap[E2n + tc*8 + 4];

        float* dst = g_h + ((size_t)h*ROWS + row0) * E2n;
        #pragma unroll
        for (int r = 0; r < 8; ++r) {
            float2 v0 = unpk(acc[r*4+0]);
            float2 v1 = unpk(acc[r*4+1]);
            float2 v2 = unpk(acc[r*4+2]);
            float2 v3 = unpk(acc[r*4+3]);
            size_t off = (size_t)(tr*8 + r)*E2n + tc*8;
            *(float4*)&dst[off]     = make_float4(v0.x, v0.y, v1.x, v1.y);
            *(float4*)&dst[off + 4] = make_float4(v2.x, v2.y, v3.x, v3.y);

            float pi = v0.x*ai0.x + v0.y*ai0.y + v1.x*ai0.z + v1.y*ai0.w
                     + v2.x*ai1.x + v2.y*ai1.y + v3.x*ai1.z + v3.y*ai1.w;
            float pj = v0.x*aj0.x + v0.y*aj0.y + v1.x*aj0.z + v1.y*aj0.w
                     + v2.x*aj1.x + v2.y*aj1.y + v3.x*aj1.z + v3.y*aj1.w;
            #pragma unroll
            for (int o = 8; o > 0; o >>= 1) {
                pi += __shfl_xor_sync(0xffffffffu, pi, o);
                pj += __shfl_xor_sync(0xffffffffu, pj, o);
            }
            if (tc == 0) {
                size_t gi = (size_t)h*ROWS + row0 + tr*8 + r;
                g_si[gi] = pi;
                g_sj[gi] = pj;
            }
        }
    }
}

// ---------------------------------------------------------------------------
// Kernel 2: fused masked-softmax attention + attn @ h.  CTA per (h, b).
// 128-row tiles, transposed prob tile, 8x8 thread tile with f32x2.
// ---------------------------------------------------------------------------
__global__ __launch_bounds__(256) void k_attn(const float* __restrict__ adj,
                                              float* __restrict__ out) {
    extern __shared__ float smem[];
    float* hs     = smem;                 // 200*128
    float* attnT  = hs + Fn*E2n;          // 200*AP  (attnT[y*AP + rowInTile])
    float* sjs    = attnT + Fn*AP;        // 200
    float* sis    = sjs + Fn;             // 200
    float* rscale = sis + Fn;             // 128

    int h = blockIdx.x, b = blockIdx.y;
    int tid = threadIdx.x;
    size_t base = (size_t)h*ROWS + (size_t)b*Fn;

    const float4* hg = (const float4*)(g_h + base * E2n);
    float4* hs4 = (float4*)hs;
    for (int i = tid; i < Fn*E2n/4; i += 256) hs4[i] = hg[i];
    for (int i = tid; i < Fn; i += 256) { sjs[i] = g_sj[base + i]; sis[i] = g_si[base + i]; }
    __syncthreads();

    int warp = tid >> 5, lane = tid & 31;
    int tr = tid >> 4;            // rows rt = tr*8 .. tr*8+7
    int tc = tid & 15;            // cols tc*8 .. tc*8+7

    for (int t0 = 0; t0 < Fn; t0 += 128) {
        int valid = Fn - t0; if (valid > 128) valid = 128;

        // ---- score phase: warp handles rows rt = rr*8 + warp ----
        #pragma unroll 1
        for (int rr = 0; rr < 16; ++rr) {
            int rt = rr*8 + warp;
            if (rt < valid) {
                int f = t0 + rt;
                float sif = sis[f];
                const float* adjrow = adj + (size_t)f * Fn;
                float s[7];
                #pragma unroll
                for (int j = 0; j < 7; ++j) {
                    int y = j*32 + lane;
                    if (y < Fn) {
                        float z = sif + sjs[y];
                        float e = (z > 0.f) ? z : ALPHAc * z;
                        float m = adjrow[y];
                        float mk = (m > 0.f) ? m : NEGc;
                        s[j] = e * mk;
                    } else s[j] = -INFINITY;
                }
                float mx = s[0];
                #pragma unroll
                for (int j = 1; j < 7; ++j) mx = fmaxf(mx, s[j]);
                #pragma unroll
                for (int o = 16; o > 0; o >>= 1) mx = fmaxf(mx, __shfl_xor_sync(0xffffffffu, mx, o));
                float p[7], sum = 0.f;
                #pragma unroll
                for (int j = 0; j < 7; ++j) { p[j] = __expf(s[j] - mx); sum += p[j]; }
                #pragma unroll
                for (int o = 16; o > 0; o >>= 1) sum += __shfl_xor_sync(0xffffffffu, sum, o);
                #pragma unroll
                for (int j = 0; j < 7; ++j) {
                    int y = j*32 + lane;
                    if (y < Fn) attnT[y*AP + rt] = p[j];
                }
                if (lane == 0) rscale[rt] = 1.f / sum;
            }
        }
        __syncthreads();

        // ---- GEMM phase: out_tile[128x128] = attn(128x200) @ hs(200x128) ----
        ull acc[32];
        #pragma unroll
        for (int i = 0; i < 32; ++i) acc[i] = 0ull;

        #pragma unroll 2
        for (int y = 0; y < Fn; ++y) {
            float4 av0 = *(const float4*)&attnT[y*AP + tr*8];
            float4 av1 = *(const float4*)&attnT[y*AP + tr*8 + 4];
            double2 h0 = *(const double2*)&hs[y*E2n + tc*8];
            double2 h1 = *(const double2*)&hs[y*E2n + tc*8 + 4];
            ull hv0 = d2l(h0.x), hv1 = d2l(h0.y), hv2 = d2l(h1.x), hv3 = d2l(h1.y);
            float avs[8] = {av0.x, av0.y, av0.z, av0.w, av1.x, av1.y, av1.z, av1.w};
            #pragma unroll
            for (int r = 0; r < 8; ++r) {
                ull ad = dup2(avs[r]);
                fma2(acc[r*4+0], ad, hv0);
                fma2(acc[r*4+1], ad, hv1);
                fma2(acc[r*4+2], ad, hv2);
                fma2(acc[r*4+3], ad, hv3);
            }
        }

        #pragma unroll
        for (int r = 0; r < 8; ++r) {
            int rt = tr*8 + r;
            if (rt < valid) {
                int f = t0 + rt;
                float sc = rscale[rt];
                float2 v0 = unpk(acc[r*4+0]);
                float2 v1 = unpk(acc[r*4+1]);
                float2 v2 = unpk(acc[r*4+2]);
                float2 v3 = unpk(acc[r*4+3]);
                size_t o = ((size_t)b*Fn + f) * (Hn*E2n) + (size_t)h*E2n + tc*8;
                *(float4*)&out[o]     = make_float4(v0.x*sc, v0.y*sc, v1.x*sc, v1.y*sc);
                *(float4*)&out[o + 4] = make_float4(v2.x*sc, v2.y*sc, v3.x*sc, v3.y*sc);
            }
        }
        __syncthreads();
    }
}

// ---------------------------------------------------------------------------

extern "C" void kernel_launch(void* const* d_in, const int* in_sizes, int n_in,
                              void* d_out, int out_size) {
    const float* x   = (const float*)d_in[0];
    const float* adj = (const float*)d_in[1];
    const float* W   = (const float*)d_in[2];
    const float* a   = (const float*)d_in[3];
    float* out = (float*)d_out;

    const int SMEM_A = (128*65 + 64*128) * 4;                      // 66,048 B
    const int SMEM_B = (Fn*E2n + Fn*AP + Fn + Fn + 128) * 4;       // 210,112 B
    cudaFuncSetAttribute(k_proj, cudaFuncAttributeMaxDynamicSharedMemorySize, SMEM_A);
    cudaFuncSetAttribute(k_attn, cudaFuncAttributeMaxDynamicSharedMemorySize, SMEM_B);

    k_proj<<<ROWS/128, 256, SMEM_A>>>(x, W, a);             // 400 CTAs
    k_attn<<<dim3(Hn, Bn), 256, SMEM_B>>>(adj, out);        // 1,024 CTAs
}